// round 2
// baseline (speedup 1.0000x reference)
#include <cuda_runtime.h>
#include <cstdint>

// VQExpert fused kernel, fp32 with packed fma.rn.f32x2.
// Round 2: 8 rows/warp, conflict-free weight LDS (split-column lane ownership),
// float4 activation broadcasts, quad-packed Wp/codebook, smem z-broadcast argmin.

typedef unsigned long long ull;
#define FULLMASK 0xffffffffu

constexpr int NROW   = 500000;
constexpr int WARPS  = 6;
constexpr int RPW    = 8;                       // rows per warp
constexpr int TILE   = WARPS * RPW;             // 48
constexpr int NTILES = (NROW + TILE - 1) / TILE; // 10417 (last tile partial)

// smem layout (floats)
// WD2/WU2/WO2: per-k-pair blocks of 256 floats: [ (k>>1)*256 + j*2 + (k&1) ]
// WP2: quad-packed: [ (k>>2)*128 + c*4 + (k&3) ]
// CB : quad-packed: [ (d>>2)*1024 + c*4 + (d&3) ]
constexpr int O_WD2 = 0;
constexpr int O_WU2 = 16384;
constexpr int O_WP2 = 32768;
constexpr int O_WO2 = 36864;
constexpr int O_CB  = 40960;
constexpr int O_CN  = 49152;
constexpr int O_BD  = 49408;
constexpr int O_BP  = 49536;
constexpr int O_BO  = 49568;
constexpr int O_BU  = 49696;
constexpr int O_TS  = 49824;                    // 6 warps x 8 rows x 128
constexpr int SMEM_FLOATS = O_TS + WARPS * RPW * 128;   // 55968
constexpr int SMEM_BYTES  = SMEM_FLOATS * 4;            // 223,872 B

__device__ __forceinline__ ull ffma2(ull a, ull b, ull c) {
    ull d;
    asm("fma.rn.f32x2 %0, %1, %2, %3;" : "=l"(d) : "l"(a), "l"(b), "l"(c));
    return d;
}
__device__ __forceinline__ float f2sum(ull v) {
    float a, b;
    asm("mov.b64 {%0, %1}, %2;" : "=f"(a), "=f"(b) : "l"(v));
    return a + b;
}

__global__ void __launch_bounds__(192, 1)
vq_expert_kernel(const float* __restrict__ x,
                 const float* __restrict__ Wd, const float* __restrict__ bd,
                 const float* __restrict__ Wp, const float* __restrict__ bp,
                 const float* __restrict__ cb,
                 const float* __restrict__ Wo, const float* __restrict__ bo,
                 const float* __restrict__ Wu, const float* __restrict__ bu,
                 float* __restrict__ out)
{
    extern __shared__ float sm[];
    const int tid = threadIdx.x;

    // ---------------- stage weights (once per CTA) ----------------
    for (int i = tid; i < 128 * 128; i += 192) {
        int j = i >> 7, k = i & 127;
        int dst = (k >> 1) * 256 + j * 2 + (k & 1);
        sm[O_WD2 + dst] = Wd[i];
        sm[O_WU2 + dst] = Wu[i];
    }
    for (int i = tid; i < 4096; i += 192) {
        { int c = i >> 7, k = i & 127; sm[O_WP2 + (k >> 2) * 128 + c * 4 + (k & 3)] = Wp[i]; }
        { int j = i >> 5, k = i & 31;  sm[O_WO2 + (k >> 1) * 256 + j * 2 + (k & 1)] = Wo[i]; }
    }
    for (int i = tid; i < 256 * 32; i += 192) {
        int c = i >> 5, d = i & 31;
        sm[O_CB + (d >> 2) * 1024 + c * 4 + (d & 3)] = cb[i];
    }
    for (int c = tid; c < 256; c += 192) {    // code norms ||c||^2
        float s = 0.f;
        #pragma unroll 8
        for (int d = 0; d < 32; d++) { float v = cb[c * 32 + d]; s = fmaf(v, v, s); }
        sm[O_CN + c] = s;
    }
    if (tid < 128) { sm[O_BD + tid] = bd[tid]; sm[O_BO + tid] = bo[tid]; sm[O_BU + tid] = bu[tid]; }
    if (tid < 32)  { sm[O_BP + tid] = bp[tid]; }
    if (blockIdx.x == 0 && tid == 0)
        out[(size_t)NROW * 128 + NROW] = 0.0f;    // commit_loss == 0 exactly
    __syncthreads();

    const int wid  = tid >> 5;
    const int lane = tid & 31;
    float* myts = sm + O_TS + wid * (RPW * 128);

    // this lane owns output cols {2l, 2l+1, 64+2l, 64+2l+1}
    const float2 bd0 = *(const float2*)(sm + O_BD + 2 * lane);
    const float2 bd1 = *(const float2*)(sm + O_BD + 64 + 2 * lane);
    const float2 bo0 = *(const float2*)(sm + O_BO + 2 * lane);
    const float2 bo1 = *(const float2*)(sm + O_BO + 64 + 2 * lane);
    const float2 bu0 = *(const float2*)(sm + O_BU + 2 * lane);
    const float2 bu1 = *(const float2*)(sm + O_BU + 64 + 2 * lane);
    const float  bpv = sm[O_BP + lane];
    float cn[8];
    #pragma unroll
    for (int i = 0; i < 8; i++) cn[i] = sm[O_CN + i * 32 + lane];

    float* outY = out;
    float* outI = out + (size_t)NROW * 128;

    for (int tile = blockIdx.x; tile < NTILES; tile += gridDim.x) {
        const int row0 = tile * TILE + wid * RPW;

        // -------- stage x: 8 rows, coalesced float4 --------
        #pragma unroll
        for (int r = 0; r < RPW; r++) {
            if (row0 + r < NROW) {
                float4 v = ((const float4*)(x + (size_t)(row0 + r) * 128))[lane];
                ((float4*)(myts + r * 128))[lane] = v;
            }
        }
        __syncwarp();

        // -------- phase A: h = x @ Wd^T (+bd) --------
        ull acc[RPW][4];
        #pragma unroll
        for (int r = 0; r < RPW; r++)
            #pragma unroll
            for (int t = 0; t < 4; t++) acc[r][t] = 0ull;

        #pragma unroll 4
        for (int pp = 0; pp < 32; pp++) {
            const float* b0 = sm + O_WD2 + (2 * pp) * 256;
            const float* b1 = b0 + 256;
            ulonglong2 wa0 = *(const ulonglong2*)(b0 + 4 * lane);
            ulonglong2 wb0 = *(const ulonglong2*)(b0 + 128 + 4 * lane);
            ulonglong2 wa1 = *(const ulonglong2*)(b1 + 4 * lane);
            ulonglong2 wb1 = *(const ulonglong2*)(b1 + 128 + 4 * lane);
            #pragma unroll
            for (int r = 0; r < RPW; r++) {
                ulonglong2 xv = *(const ulonglong2*)(myts + r * 128 + 4 * pp);
                acc[r][0] = ffma2(xv.x, wa0.x, acc[r][0]);
                acc[r][1] = ffma2(xv.x, wa0.y, acc[r][1]);
                acc[r][2] = ffma2(xv.x, wb0.x, acc[r][2]);
                acc[r][3] = ffma2(xv.x, wb0.y, acc[r][3]);
                acc[r][0] = ffma2(xv.y, wa1.x, acc[r][0]);
                acc[r][1] = ffma2(xv.y, wa1.y, acc[r][1]);
                acc[r][2] = ffma2(xv.y, wb1.x, acc[r][2]);
                acc[r][3] = ffma2(xv.y, wb1.y, acc[r][3]);
            }
        }
        __syncwarp();
        #pragma unroll
        for (int r = 0; r < RPW; r++) {
            float2 h0, h1;
            h0.x = bd0.x + f2sum(acc[r][0]);
            h0.y = bd0.y + f2sum(acc[r][1]);
            h1.x = bd1.x + f2sum(acc[r][2]);
            h1.y = bd1.y + f2sum(acc[r][3]);
            *(float2*)(myts + r * 128 + 2 * lane) = h0;
            *(float2*)(myts + r * 128 + 64 + 2 * lane) = h1;
        }
        __syncwarp();

        // -------- phase B: z = h @ Wp^T (+bp), lane = z-column --------
        ull za[RPW];
        #pragma unroll
        for (int r = 0; r < RPW; r++) za[r] = 0ull;
        #pragma unroll 4
        for (int kq = 0; kq < 32; kq++) {
            ulonglong2 w = *(const ulonglong2*)(sm + O_WP2 + kq * 128 + 4 * lane);
            #pragma unroll
            for (int r = 0; r < RPW; r++) {
                ulonglong2 h2 = *(const ulonglong2*)(myts + r * 128 + 4 * kq);
                za[r] = ffma2(h2.x, w.x, za[r]);
                za[r] = ffma2(h2.y, w.y, za[r]);
            }
        }
        __syncwarp();
        #pragma unroll
        for (int r = 0; r < RPW; r++)
            myts[r * 128 + lane] = bpv + f2sum(za[r]);   // z overwrites h cols 0..31
        __syncwarp();

        // -------- phase C: argmin_c ||c||^2 - 2 z.c, 4 rows at a time --------
        int bc[RPW];
        #pragma unroll
        for (int hh = 0; hh < 2; hh++) {
            ull da[4][8];
            #pragma unroll
            for (int r = 0; r < 4; r++)
                #pragma unroll
                for (int i = 0; i < 8; i++) da[r][i] = 0ull;

            #pragma unroll
            for (int dq = 0; dq < 8; dq++) {
                ulonglong2 zq[4];
                #pragma unroll
                for (int r = 0; r < 4; r++)
                    zq[r] = *(const ulonglong2*)(myts + (hh * 4 + r) * 128 + 4 * dq);
                #pragma unroll
                for (int i = 0; i < 8; i++) {
                    ulonglong2 c2 = *(const ulonglong2*)(sm + O_CB + dq * 1024 + (i * 32 + lane) * 4);
                    #pragma unroll
                    for (int r = 0; r < 4; r++) {
                        da[r][i] = ffma2(zq[r].x, c2.x, da[r][i]);
                        da[r][i] = ffma2(zq[r].y, c2.y, da[r][i]);
                    }
                }
            }
            #pragma unroll
            for (int r = 0; r < 4; r++) {
                float bs = 3.4e38f; int bi = 0;
                #pragma unroll
                for (int i = 0; i < 8; i++) {
                    float s = cn[i] - 2.0f * f2sum(da[r][i]);
                    int c = (i << 5) | lane;
                    if (s < bs) { bs = s; bi = c; }
                }
                #pragma unroll
                for (int off = 16; off > 0; off >>= 1) {
                    float s2 = __shfl_xor_sync(FULLMASK, bs, off);
                    int   c2 = __shfl_xor_sync(FULLMASK, bi, off);
                    if (s2 < bs || (s2 == bs && c2 < bi)) { bs = s2; bi = c2; }
                }
                bc[hh * 4 + r] = bi;   // warp-uniform
            }
        }

        // -------- phase D: v = cb[bc] @ Wo^T (+bo) --------
        ull va[RPW][4];
        #pragma unroll
        for (int r = 0; r < RPW; r++)
            #pragma unroll
            for (int t = 0; t < 4; t++) va[r][t] = 0ull;

        #pragma unroll 4
        for (int j = 0; j < 16; j++) {         // d-pair index
            const float* wb = sm + O_WO2 + j * 256;
            ulonglong2 wa = *(const ulonglong2*)(wb + 4 * lane);
            ulonglong2 wz = *(const ulonglong2*)(wb + 128 + 4 * lane);
            #pragma unroll
            for (int r = 0; r < RPW; r++) {
                ull q2 = *(const ull*)(sm + O_CB + (j >> 1) * 1024 + bc[r] * 4 + (j & 1) * 2);
                va[r][0] = ffma2(q2, wa.x, va[r][0]);
                va[r][1] = ffma2(q2, wa.y, va[r][1]);
                va[r][2] = ffma2(q2, wz.x, va[r][2]);
                va[r][3] = ffma2(q2, wz.y, va[r][3]);
            }
        }
        __syncwarp();
        #pragma unroll
        for (int r = 0; r < RPW; r++) {
            float2 v0, v1;
            v0.x = bo0.x + f2sum(va[r][0]);
            v0.y = bo0.y + f2sum(va[r][1]);
            v1.x = bo1.x + f2sum(va[r][2]);
            v1.y = bo1.y + f2sum(va[r][3]);
            *(float2*)(myts + r * 128 + 2 * lane) = v0;
            *(float2*)(myts + r * 128 + 64 + 2 * lane) = v1;
        }
        __syncwarp();

        // -------- phase E: y = clamp(v @ Wu^T + bu) --------
        ull ea[RPW][4];
        #pragma unroll
        for (int r = 0; r < RPW; r++)
            #pragma unroll
            for (int t = 0; t < 4; t++) ea[r][t] = 0ull;

        #pragma unroll 4
        for (int pp = 0; pp < 32; pp++) {
            const float* b0 = sm + O_WU2 + (2 * pp) * 256;
            const float* b1 = b0 + 256;
            ulonglong2 wa0 = *(const ulonglong2*)(b0 + 4 * lane);
            ulonglong2 wb0 = *(const ulonglong2*)(b0 + 128 + 4 * lane);
            ulonglong2 wa1 = *(const ulonglong2*)(b1 + 4 * lane);
            ulonglong2 wb1 = *(const ulonglong2*)(b1 + 128 + 4 * lane);
            #pragma unroll
            for (int r = 0; r < RPW; r++) {
                ulonglong2 vv = *(const ulonglong2*)(myts + r * 128 + 4 * pp);
                ea[r][0] = ffma2(vv.x, wa0.x, ea[r][0]);
                ea[r][1] = ffma2(vv.x, wa0.y, ea[r][1]);
                ea[r][2] = ffma2(vv.x, wb0.x, ea[r][2]);
                ea[r][3] = ffma2(vv.x, wb0.y, ea[r][3]);
                ea[r][0] = ffma2(vv.y, wa1.x, ea[r][0]);
                ea[r][1] = ffma2(vv.y, wa1.y, ea[r][1]);
                ea[r][2] = ffma2(vv.y, wb1.x, ea[r][2]);
                ea[r][3] = ffma2(vv.y, wb1.y, ea[r][3]);
            }
        }
        #pragma unroll
        for (int r = 0; r < RPW; r++) {
            if (row0 + r < NROW) {
                float2 y0, y1;
                y0.x = fminf(fmaxf(bu0.x + f2sum(ea[r][0]), -1.0f), 1.0f);
                y0.y = fminf(fmaxf(bu0.y + f2sum(ea[r][1]), -1.0f), 1.0f);
                y1.x = fminf(fmaxf(bu1.x + f2sum(ea[r][2]), -1.0f), 1.0f);
                y1.y = fminf(fmaxf(bu1.y + f2sum(ea[r][3]), -1.0f), 1.0f);
                float* yr = outY + (size_t)(row0 + r) * 128;
                *(float2*)(yr + 2 * lane) = y0;
                *(float2*)(yr + 64 + 2 * lane) = y1;
            }
        }
        if (lane == 0) {
            #pragma unroll
            for (int r = 0; r < RPW; r++)
                if (row0 + r < NROW) outI[row0 + r] = (float)bc[r];
        }
        __syncwarp();
    }
}

extern "C" void kernel_launch(void* const* d_in, const int* in_sizes, int n_in,
                              void* d_out, int out_size)
{
    const float* x  = (const float*)d_in[0];
    const float* Wd = (const float*)d_in[1];
    const float* bd = (const float*)d_in[2];
    const float* Wp = (const float*)d_in[3];
    const float* bp = (const float*)d_in[4];
    const float* cb = (const float*)d_in[5];
    const float* Wo = (const float*)d_in[6];
    const float* bo = (const float*)d_in[7];
    const float* Wu = (const float*)d_in[8];
    const float* bu = (const float*)d_in[9];
    float* out = (float*)d_out;

    cudaFuncSetAttribute(vq_expert_kernel,
                         cudaFuncAttributeMaxDynamicSharedMemorySize, SMEM_BYTES);

    vq_expert_kernel<<<148, 192, SMEM_BYTES>>>(x, Wd, bd, Wp, bp, cb, Wo, bo, Wu, bu, out);
}

// round 3
// speedup vs baseline: 1.5241x; 1.5241x over previous
#include <cuda_runtime.h>
#include <cstdint>

// VQExpert fused kernel, fp32 with packed fma.rn.f32x2.
// Round 3: conflict-free split-column weight layout (R2) + RPW=4 (R1 reg budget)
// + 384 threads / 12 warps for latency hiding. Phase C in 2-row halves.

typedef unsigned long long ull;
#define FULLMASK 0xffffffffu

constexpr int NROW   = 500000;
constexpr int WARPS  = 12;
constexpr int RPW    = 4;                        // rows per warp
constexpr int TILE   = WARPS * RPW;              // 48
constexpr int NTILES = (NROW + TILE - 1) / TILE; // 10417 (last tile partial)

// smem layout (floats)
// WD2/WU2/WO2: per-k-pair blocks of 256 floats: [ (k>>1)*256 + j*2 + (k&1) ]
// WP2: quad-packed: [ (k>>2)*128 + c*4 + (k&3) ]
// CB : quad-packed: [ (d>>2)*1024 + c*4 + (d&3) ]
constexpr int O_WD2 = 0;
constexpr int O_WU2 = 16384;
constexpr int O_WP2 = 32768;
constexpr int O_WO2 = 36864;
constexpr int O_CB  = 40960;
constexpr int O_CN  = 49152;
constexpr int O_BD  = 49408;
constexpr int O_BP  = 49536;
constexpr int O_BO  = 49568;
constexpr int O_BU  = 49696;
constexpr int O_TS  = 49824;                    // 12 warps x 4 rows x 128
constexpr int SMEM_FLOATS = O_TS + WARPS * RPW * 128;   // 55968
constexpr int SMEM_BYTES  = SMEM_FLOATS * 4;            // 223,872 B

__device__ __forceinline__ ull ffma2(ull a, ull b, ull c) {
    ull d;
    asm("fma.rn.f32x2 %0, %1, %2, %3;" : "=l"(d) : "l"(a), "l"(b), "l"(c));
    return d;
}
__device__ __forceinline__ float f2sum(ull v) {
    float a, b;
    asm("mov.b64 {%0, %1}, %2;" : "=f"(a), "=f"(b) : "l"(v));
    return a + b;
}

__global__ void __launch_bounds__(384, 1)
vq_expert_kernel(const float* __restrict__ x,
                 const float* __restrict__ Wd, const float* __restrict__ bd,
                 const float* __restrict__ Wp, const float* __restrict__ bp,
                 const float* __restrict__ cb,
                 const float* __restrict__ Wo, const float* __restrict__ bo,
                 const float* __restrict__ Wu, const float* __restrict__ bu,
                 float* __restrict__ out)
{
    extern __shared__ float sm[];
    const int tid = threadIdx.x;

    // ---------------- stage weights (once per CTA) ----------------
    for (int i = tid; i < 128 * 128; i += 384) {
        int j = i >> 7, k = i & 127;
        int dst = (k >> 1) * 256 + j * 2 + (k & 1);
        sm[O_WD2 + dst] = Wd[i];
        sm[O_WU2 + dst] = Wu[i];
    }
    for (int i = tid; i < 4096; i += 384) {
        { int c = i >> 7, k = i & 127; sm[O_WP2 + (k >> 2) * 128 + c * 4 + (k & 3)] = Wp[i]; }
        { int j = i >> 5, k = i & 31;  sm[O_WO2 + (k >> 1) * 256 + j * 2 + (k & 1)] = Wo[i]; }
    }
    for (int i = tid; i < 256 * 32; i += 384) {
        int c = i >> 5, d = i & 31;
        sm[O_CB + (d >> 2) * 1024 + c * 4 + (d & 3)] = cb[i];
    }
    for (int c = tid; c < 256; c += 384) {    // code norms ||c||^2
        float s = 0.f;
        #pragma unroll 8
        for (int d = 0; d < 32; d++) { float v = cb[c * 32 + d]; s = fmaf(v, v, s); }
        sm[O_CN + c] = s;
    }
    if (tid < 128) { sm[O_BD + tid] = bd[tid]; sm[O_BO + tid] = bo[tid]; sm[O_BU + tid] = bu[tid]; }
    else if (tid >= 128 && tid < 160) { sm[O_BP + tid - 128] = bp[tid - 128]; }
    if (blockIdx.x == 0 && tid == 0)
        out[(size_t)NROW * 128 + NROW] = 0.0f;    // commit_loss == 0 exactly
    __syncthreads();

    const int wid  = tid >> 5;
    const int lane = tid & 31;
    float* myts = sm + O_TS + wid * (RPW * 128);

    // this lane owns output cols {2l, 2l+1, 64+2l, 64+2l+1}
    const float2 bd0 = *(const float2*)(sm + O_BD + 2 * lane);
    const float2 bd1 = *(const float2*)(sm + O_BD + 64 + 2 * lane);
    const float2 bo0 = *(const float2*)(sm + O_BO + 2 * lane);
    const float2 bo1 = *(const float2*)(sm + O_BO + 64 + 2 * lane);
    const float2 bu0 = *(const float2*)(sm + O_BU + 2 * lane);
    const float2 bu1 = *(const float2*)(sm + O_BU + 64 + 2 * lane);
    const float  bpv = sm[O_BP + lane];
    float cn[8];
    #pragma unroll
    for (int i = 0; i < 8; i++) cn[i] = sm[O_CN + i * 32 + lane];

    float* outY = out;
    float* outI = out + (size_t)NROW * 128;

    for (int tile = blockIdx.x; tile < NTILES; tile += gridDim.x) {
        const int row0 = tile * TILE + wid * RPW;
        const bool full = (row0 + RPW <= NROW);

        // -------- stage x: 4 rows, coalesced float4 --------
        #pragma unroll
        for (int r = 0; r < RPW; r++) {
            if (full || row0 + r < NROW) {
                float4 v = ((const float4*)(x + (size_t)(row0 + r) * 128))[lane];
                ((float4*)(myts + r * 128))[lane] = v;
            }
        }
        __syncwarp();

        // -------- phase A: h = x @ Wd^T (+bd) --------
        ull acc[RPW][4];
        #pragma unroll
        for (int r = 0; r < RPW; r++)
            #pragma unroll
            for (int t = 0; t < 4; t++) acc[r][t] = 0ull;

        #pragma unroll 4
        for (int pp = 0; pp < 32; pp++) {
            const float* b0 = sm + O_WD2 + (2 * pp) * 256;
            const float* b1 = b0 + 256;
            ulonglong2 wa0 = *(const ulonglong2*)(b0 + 4 * lane);
            ulonglong2 wb0 = *(const ulonglong2*)(b0 + 128 + 4 * lane);
            ulonglong2 wa1 = *(const ulonglong2*)(b1 + 4 * lane);
            ulonglong2 wb1 = *(const ulonglong2*)(b1 + 128 + 4 * lane);
            #pragma unroll
            for (int r = 0; r < RPW; r++) {
                ulonglong2 xv = *(const ulonglong2*)(myts + r * 128 + 4 * pp);
                acc[r][0] = ffma2(xv.x, wa0.x, acc[r][0]);
                acc[r][1] = ffma2(xv.x, wa0.y, acc[r][1]);
                acc[r][2] = ffma2(xv.x, wb0.x, acc[r][2]);
                acc[r][3] = ffma2(xv.x, wb0.y, acc[r][3]);
                acc[r][0] = ffma2(xv.y, wa1.x, acc[r][0]);
                acc[r][1] = ffma2(xv.y, wa1.y, acc[r][1]);
                acc[r][2] = ffma2(xv.y, wb1.x, acc[r][2]);
                acc[r][3] = ffma2(xv.y, wb1.y, acc[r][3]);
            }
        }
        __syncwarp();
        #pragma unroll
        for (int r = 0; r < RPW; r++) {
            float2 h0, h1;
            h0.x = bd0.x + f2sum(acc[r][0]);
            h0.y = bd0.y + f2sum(acc[r][1]);
            h1.x = bd1.x + f2sum(acc[r][2]);
            h1.y = bd1.y + f2sum(acc[r][3]);
            *(float2*)(myts + r * 128 + 2 * lane) = h0;
            *(float2*)(myts + r * 128 + 64 + 2 * lane) = h1;
        }
        __syncwarp();

        // -------- phase B: z = h @ Wp^T (+bp), lane = z-column --------
        ull za[RPW];
        #pragma unroll
        for (int r = 0; r < RPW; r++) za[r] = 0ull;
        #pragma unroll 4
        for (int kq = 0; kq < 32; kq++) {
            ulonglong2 w = *(const ulonglong2*)(sm + O_WP2 + kq * 128 + 4 * lane);
            #pragma unroll
            for (int r = 0; r < RPW; r++) {
                ulonglong2 h2 = *(const ulonglong2*)(myts + r * 128 + 4 * kq);
                za[r] = ffma2(h2.x, w.x, za[r]);
                za[r] = ffma2(h2.y, w.y, za[r]);
            }
        }
        __syncwarp();
        #pragma unroll
        for (int r = 0; r < RPW; r++)
            myts[r * 128 + lane] = bpv + f2sum(za[r]);   // z overwrites h cols 0..31
        __syncwarp();

        // -------- phase C: argmin_c ||c||^2 - 2 z.c, 2 rows at a time --------
        int bc[RPW];
        #pragma unroll
        for (int hh = 0; hh < RPW / 2; hh++) {
            ull da[2][8];
            #pragma unroll
            for (int r = 0; r < 2; r++)
                #pragma unroll
                for (int i = 0; i < 8; i++) da[r][i] = 0ull;

            #pragma unroll
            for (int dq = 0; dq < 8; dq++) {
                ulonglong2 zq[2];
                #pragma unroll
                for (int r = 0; r < 2; r++)
                    zq[r] = *(const ulonglong2*)(myts + (hh * 2 + r) * 128 + 4 * dq);
                #pragma unroll
                for (int i = 0; i < 8; i++) {
                    ulonglong2 c2 = *(const ulonglong2*)(sm + O_CB + dq * 1024 + (i * 32 + lane) * 4);
                    #pragma unroll
                    for (int r = 0; r < 2; r++) {
                        da[r][i] = ffma2(zq[r].x, c2.x, da[r][i]);
                        da[r][i] = ffma2(zq[r].y, c2.y, da[r][i]);
                    }
                }
            }
            #pragma unroll
            for (int r = 0; r < 2; r++) {
                float bs = 3.4e38f; int bi = 0;
                #pragma unroll
                for (int i = 0; i < 8; i++) {
                    float s = cn[i] - 2.0f * f2sum(da[r][i]);
                    int c = (i << 5) | lane;
                    if (s < bs) { bs = s; bi = c; }
                }
                #pragma unroll
                for (int off = 16; off > 0; off >>= 1) {
                    float s2 = __shfl_xor_sync(FULLMASK, bs, off);
                    int   c2 = __shfl_xor_sync(FULLMASK, bi, off);
                    if (s2 < bs || (s2 == bs && c2 < bi)) { bs = s2; bi = c2; }
                }
                bc[hh * 2 + r] = bi;   // warp-uniform
            }
        }

        // -------- phase D: v = cb[bc] @ Wo^T (+bo) --------
        ull va[RPW][4];
        #pragma unroll
        for (int r = 0; r < RPW; r++)
            #pragma unroll
            for (int t = 0; t < 4; t++) va[r][t] = 0ull;

        #pragma unroll 4
        for (int j = 0; j < 16; j++) {         // d-pair index
            const float* wb = sm + O_WO2 + j * 256;
            ulonglong2 wa = *(const ulonglong2*)(wb + 4 * lane);
            ulonglong2 wz = *(const ulonglong2*)(wb + 128 + 4 * lane);
            #pragma unroll
            for (int r = 0; r < RPW; r++) {
                ull q2 = *(const ull*)(sm + O_CB + (j >> 1) * 1024 + bc[r] * 4 + (j & 1) * 2);
                va[r][0] = ffma2(q2, wa.x, va[r][0]);
                va[r][1] = ffma2(q2, wa.y, va[r][1]);
                va[r][2] = ffma2(q2, wz.x, va[r][2]);
                va[r][3] = ffma2(q2, wz.y, va[r][3]);
            }
        }
        __syncwarp();
        #pragma unroll
        for (int r = 0; r < RPW; r++) {
            float2 v0, v1;
            v0.x = bo0.x + f2sum(va[r][0]);
            v0.y = bo0.y + f2sum(va[r][1]);
            v1.x = bo1.x + f2sum(va[r][2]);
            v1.y = bo1.y + f2sum(va[r][3]);
            *(float2*)(myts + r * 128 + 2 * lane) = v0;
            *(float2*)(myts + r * 128 + 64 + 2 * lane) = v1;
        }
        __syncwarp();

        // -------- phase E: y = clamp(v @ Wu^T + bu) --------
        ull ea[RPW][4];
        #pragma unroll
        for (int r = 0; r < RPW; r++)
            #pragma unroll
            for (int t = 0; t < 4; t++) ea[r][t] = 0ull;

        #pragma unroll 4
        for (int pp = 0; pp < 32; pp++) {
            const float* b0 = sm + O_WU2 + (2 * pp) * 256;
            const float* b1 = b0 + 256;
            ulonglong2 wa0 = *(const ulonglong2*)(b0 + 4 * lane);
            ulonglong2 wb0 = *(const ulonglong2*)(b0 + 128 + 4 * lane);
            ulonglong2 wa1 = *(const ulonglong2*)(b1 + 4 * lane);
            ulonglong2 wb1 = *(const ulonglong2*)(b1 + 128 + 4 * lane);
            #pragma unroll
            for (int r = 0; r < RPW; r++) {
                ulonglong2 vv = *(const ulonglong2*)(myts + r * 128 + 4 * pp);
                ea[r][0] = ffma2(vv.x, wa0.x, ea[r][0]);
                ea[r][1] = ffma2(vv.x, wa0.y, ea[r][1]);
                ea[r][2] = ffma2(vv.x, wb0.x, ea[r][2]);
                ea[r][3] = ffma2(vv.x, wb0.y, ea[r][3]);
                ea[r][0] = ffma2(vv.y, wa1.x, ea[r][0]);
                ea[r][1] = ffma2(vv.y, wa1.y, ea[r][1]);
                ea[r][2] = ffma2(vv.y, wb1.x, ea[r][2]);
                ea[r][3] = ffma2(vv.y, wb1.y, ea[r][3]);
            }
        }
        #pragma unroll
        for (int r = 0; r < RPW; r++) {
            if (full || row0 + r < NROW) {
                float2 y0, y1;
                y0.x = fminf(fmaxf(bu0.x + f2sum(ea[r][0]), -1.0f), 1.0f);
                y0.y = fminf(fmaxf(bu0.y + f2sum(ea[r][1]), -1.0f), 1.0f);
                y1.x = fminf(fmaxf(bu1.x + f2sum(ea[r][2]), -1.0f), 1.0f);
                y1.y = fminf(fmaxf(bu1.y + f2sum(ea[r][3]), -1.0f), 1.0f);
                float* yr = outY + (size_t)(row0 + r) * 128;
                *(float2*)(yr + 2 * lane) = y0;
                *(float2*)(yr + 64 + 2 * lane) = y1;
            }
        }
        if (lane == 0) {
            #pragma unroll
            for (int r = 0; r < RPW; r++)
                if (row0 + r < NROW) outI[row0 + r] = (float)bc[r];
        }
        __syncwarp();
    }
}

extern "C" void kernel_launch(void* const* d_in, const int* in_sizes, int n_in,
                              void* d_out, int out_size)
{
    const float* x  = (const float*)d_in[0];
    const float* Wd = (const float*)d_in[1];
    const float* bd = (const float*)d_in[2];
    const float* Wp = (const float*)d_in[3];
    const float* bp = (const float*)d_in[4];
    const float* cb = (const float*)d_in[5];
    const float* Wo = (const float*)d_in[6];
    const float* bo = (const float*)d_in[7];
    const float* Wu = (const float*)d_in[8];
    const float* bu = (const float*)d_in[9];
    float* out = (float*)d_out;

    cudaFuncSetAttribute(vq_expert_kernel,
                         cudaFuncAttributeMaxDynamicSharedMemorySize, SMEM_BYTES);

    vq_expert_kernel<<<148, 384, SMEM_BYTES>>>(x, Wd, bd, Wp, bp, cb, Wo, bo, Wu, bu, out);
}

// round 4
// speedup vs baseline: 2.4769x; 1.6251x over previous
#include <cuda_runtime.h>
#include <cstdint>

// VQExpert fused kernel, round 4.
// Key change: phases D+E (v = q@Wo^T+bo ; y = clamp(v@Wu^T+bu)) are linear in q,
// and q = codebook[idx], so precompute T[256][128] = (cb@Wo^T)@Wu^T and
// B[128] = bo@Wu^T + bu in a prologue kernel. Main kernel: A (x@Wd^T), B (h@Wp^T),
// C (argmin), then y = clamp(T[idx] + B). 42% fewer FLOPs. RPW=8 for wf/ffma2 ratio.

typedef unsigned long long ull;
#define FULLMASK 0xffffffffu

constexpr int NROW   = 500000;
constexpr int WARPS  = 12;
constexpr int RPW    = 8;                        // rows per warp
constexpr int TILE   = WARPS * RPW;              // 96
constexpr int NTILES = (NROW + TILE - 1) / TILE; // 5209

// smem layout (floats)
constexpr int O_WD2 = 0;          // 128x128: [(k>>1)*256 + j*2 + (k&1)]
constexpr int O_WP2 = 16384;      // 32x128 quad-packed: [(k>>2)*128 + c*4 + (k&3)]
constexpr int O_CB  = 20480;      // codebook quad-packed: [(d>>2)*1024 + c*4 + (d&3)]
constexpr int O_CN  = 28672;      // 256 code norms
constexpr int O_BD  = 28928;
constexpr int O_BP  = 29056;
constexpr int O_TS  = 29088;      // 12 warps x 8 rows x 128
constexpr int SMEM_FLOATS = O_TS + WARPS * RPW * 128;   // 41376
constexpr int SMEM_BYTES  = SMEM_FLOATS * 4;            // 165,504 B

__device__ float g_T[256 * 128];  // fused codebook->output table
__device__ float g_B[128];        // fused bias

__device__ __forceinline__ ull ffma2(ull a, ull b, ull c) {
    ull d;
    asm("fma.rn.f32x2 %0, %1, %2, %3;" : "=l"(d) : "l"(a), "l"(b), "l"(c));
    return d;
}
__device__ __forceinline__ float f2sum(ull v) {
    float a, b;
    asm("mov.b64 {%0, %1}, %2;" : "=f"(a), "=f"(b) : "l"(v));
    return a + b;
}

// ---------------- prologue: build T and B ----------------
__global__ void __launch_bounds__(128)
vq_precompute_kernel(const float* __restrict__ cb,
                     const float* __restrict__ Wo, const float* __restrict__ bo,
                     const float* __restrict__ Wu, const float* __restrict__ bu)
{
    __shared__ float v[128];
    const int i = threadIdx.x;
    const int c = blockIdx.x;
    if (c < 256) {
        // v[j] = dot(cb[c], Wo[j])   (j = thread)
        float s = 0.f;
        #pragma unroll 8
        for (int d = 0; d < 32; d++) s = fmaf(cb[c * 32 + d], Wo[i * 32 + d], s);
        v[i] = s;
        __syncthreads();
        // T[c][i] = dot(v, Wu[i])
        float t = 0.f;
        #pragma unroll 8
        for (int j = 0; j < 128; j++) t = fmaf(v[j], Wu[i * 128 + j], t);
        g_T[c * 128 + i] = t;
    } else {
        v[i] = bo[i];
        __syncthreads();
        float t = bu[i];
        #pragma unroll 8
        for (int j = 0; j < 128; j++) t = fmaf(v[j], Wu[i * 128 + j], t);
        g_B[i] = t;
    }
}

// ---------------- main kernel ----------------
__global__ void __launch_bounds__(384, 1)
vq_expert_kernel(const float* __restrict__ x,
                 const float* __restrict__ Wd, const float* __restrict__ bd,
                 const float* __restrict__ Wp, const float* __restrict__ bp,
                 const float* __restrict__ cb,
                 float* __restrict__ out)
{
    extern __shared__ float sm[];
    const int tid = threadIdx.x;

    // stage weights once per CTA
    for (int i = tid; i < 128 * 128; i += 384) {
        int j = i >> 7, k = i & 127;
        sm[O_WD2 + (k >> 1) * 256 + j * 2 + (k & 1)] = Wd[i];
    }
    for (int i = tid; i < 4096; i += 384) {
        int c = i >> 7, k = i & 127;
        sm[O_WP2 + (k >> 2) * 128 + c * 4 + (k & 3)] = Wp[i];
    }
    for (int i = tid; i < 256 * 32; i += 384) {
        int c = i >> 5, d = i & 31;
        sm[O_CB + (d >> 2) * 1024 + c * 4 + (d & 3)] = cb[i];
    }
    for (int c = tid; c < 256; c += 384) {
        float s = 0.f;
        #pragma unroll 8
        for (int d = 0; d < 32; d++) { float v = cb[c * 32 + d]; s = fmaf(v, v, s); }
        sm[O_CN + c] = s;
    }
    if (tid < 128) sm[O_BD + tid] = bd[tid];
    else if (tid < 160) sm[O_BP + tid - 128] = bp[tid - 128];
    if (blockIdx.x == 0 && tid == 0)
        out[(size_t)NROW * 128 + NROW] = 0.0f;    // commit_loss == 0 exactly
    __syncthreads();

    const int wid  = tid >> 5;
    const int lane = tid & 31;
    float* myts = sm + O_TS + wid * (RPW * 128);

    // lane owns output cols {2l, 2l+1, 64+2l, 64+2l+1}
    const float2 bd0 = *(const float2*)(sm + O_BD + 2 * lane);
    const float2 bd1 = *(const float2*)(sm + O_BD + 64 + 2 * lane);
    const float2 gB0 = *(const float2*)(g_B + 2 * lane);
    const float2 gB1 = *(const float2*)(g_B + 64 + 2 * lane);
    const float  bpv = sm[O_BP + lane];
    float cn[8];
    #pragma unroll
    for (int i = 0; i < 8; i++) cn[i] = sm[O_CN + i * 32 + lane];

    float* outY = out;
    float* outI = out + (size_t)NROW * 128;

    for (int tile = blockIdx.x; tile < NTILES; tile += gridDim.x) {
        const int row0 = tile * TILE + wid * RPW;
        if (row0 >= NROW) continue;
        const bool full = (row0 + RPW <= NROW);

        // stage x
        #pragma unroll
        for (int r = 0; r < RPW; r++) {
            if (full || row0 + r < NROW) {
                float4 v = ((const float4*)(x + (size_t)(row0 + r) * 128))[lane];
                ((float4*)(myts + r * 128))[lane] = v;
            }
        }
        __syncwarp();

        // -------- phase A: h = x @ Wd^T (+bd) --------
        ull acc[RPW][4];
        #pragma unroll
        for (int r = 0; r < RPW; r++)
            #pragma unroll
            for (int t = 0; t < 4; t++) acc[r][t] = 0ull;

        #pragma unroll 2
        for (int pp = 0; pp < 32; pp++) {
            const float* b0 = sm + O_WD2 + (2 * pp) * 256;
            const float* b1 = b0 + 256;
            ulonglong2 wa0 = *(const ulonglong2*)(b0 + 4 * lane);
            ulonglong2 wb0 = *(const ulonglong2*)(b0 + 128 + 4 * lane);
            ulonglong2 wa1 = *(const ulonglong2*)(b1 + 4 * lane);
            ulonglong2 wb1 = *(const ulonglong2*)(b1 + 128 + 4 * lane);
            #pragma unroll
            for (int r = 0; r < RPW; r++) {
                ulonglong2 xv = *(const ulonglong2*)(myts + r * 128 + 4 * pp);
                acc[r][0] = ffma2(xv.x, wa0.x, acc[r][0]);
                acc[r][1] = ffma2(xv.x, wa0.y, acc[r][1]);
                acc[r][2] = ffma2(xv.x, wb0.x, acc[r][2]);
                acc[r][3] = ffma2(xv.x, wb0.y, acc[r][3]);
                acc[r][0] = ffma2(xv.y, wa1.x, acc[r][0]);
                acc[r][1] = ffma2(xv.y, wa1.y, acc[r][1]);
                acc[r][2] = ffma2(xv.y, wb1.x, acc[r][2]);
                acc[r][3] = ffma2(xv.y, wb1.y, acc[r][3]);
            }
        }
        __syncwarp();
        #pragma unroll
        for (int r = 0; r < RPW; r++) {
            float2 h0, h1;
            h0.x = bd0.x + f2sum(acc[r][0]);
            h0.y = bd0.y + f2sum(acc[r][1]);
            h1.x = bd1.x + f2sum(acc[r][2]);
            h1.y = bd1.y + f2sum(acc[r][3]);
            *(float2*)(myts + r * 128 + 2 * lane) = h0;
            *(float2*)(myts + r * 128 + 64 + 2 * lane) = h1;
        }
        __syncwarp();

        // -------- phase B: z = h @ Wp^T (+bp), lane = z-column --------
        ull za[RPW];
        #pragma unroll
        for (int r = 0; r < RPW; r++) za[r] = 0ull;
        #pragma unroll 4
        for (int kq = 0; kq < 32; kq++) {
            ulonglong2 w = *(const ulonglong2*)(sm + O_WP2 + kq * 128 + 4 * lane);
            #pragma unroll
            for (int r = 0; r < RPW; r++) {
                ulonglong2 h2 = *(const ulonglong2*)(myts + r * 128 + 4 * kq);
                za[r] = ffma2(h2.x, w.x, za[r]);
                za[r] = ffma2(h2.y, w.y, za[r]);
            }
        }
        __syncwarp();
        #pragma unroll
        for (int r = 0; r < RPW; r++)
            myts[r * 128 + lane] = bpv + f2sum(za[r]);   // z in cols 0..31
        __syncwarp();

        // -------- phase C: argmin_c ||c||^2 - 2 z.c, 4 rows per codebook pass --------
        int bc[RPW];
        #pragma unroll
        for (int hh = 0; hh < RPW / 4; hh++) {
            ull da[4][8];
            #pragma unroll
            for (int r = 0; r < 4; r++)
                #pragma unroll
                for (int i = 0; i < 8; i++) da[r][i] = 0ull;

            #pragma unroll 4
            for (int dq = 0; dq < 8; dq++) {
                ulonglong2 zq[4];
                #pragma unroll
                for (int r = 0; r < 4; r++)
                    zq[r] = *(const ulonglong2*)(myts + (hh * 4 + r) * 128 + 4 * dq);
                #pragma unroll
                for (int i = 0; i < 8; i++) {
                    ulonglong2 c2 = *(const ulonglong2*)(sm + O_CB + dq * 1024 + (i * 32 + lane) * 4);
                    #pragma unroll
                    for (int r = 0; r < 4; r++) {
                        da[r][i] = ffma2(zq[r].x, c2.x, da[r][i]);
                        da[r][i] = ffma2(zq[r].y, c2.y, da[r][i]);
                    }
                }
            }
            #pragma unroll
            for (int r = 0; r < 4; r++) {
                float bs = 3.4e38f; int bi = 0;
                #pragma unroll
                for (int i = 0; i < 8; i++) {
                    float s = cn[i] - 2.0f * f2sum(da[r][i]);
                    int c = (i << 5) | lane;
                    if (s < bs) { bs = s; bi = c; }
                }
                #pragma unroll
                for (int off = 16; off > 0; off >>= 1) {
                    float s2 = __shfl_xor_sync(FULLMASK, bs, off);
                    int   c2 = __shfl_xor_sync(FULLMASK, bi, off);
                    if (s2 < bs || (s2 == bs && c2 < bi)) { bs = s2; bi = c2; }
                }
                bc[hh * 4 + r] = bi;   // warp-uniform
            }
        }

        // -------- fused D+E: y = clamp(T[bc] + B) --------
        #pragma unroll
        for (int r = 0; r < RPW; r++) {
            if (full || row0 + r < NROW) {
                const float* Trow = g_T + bc[r] * 128;
                float2 t0 = *(const float2*)(Trow + 2 * lane);
                float2 t1 = *(const float2*)(Trow + 64 + 2 * lane);
                float2 y0, y1;
                y0.x = fminf(fmaxf(t0.x + gB0.x, -1.0f), 1.0f);
                y0.y = fminf(fmaxf(t0.y + gB0.y, -1.0f), 1.0f);
                y1.x = fminf(fmaxf(t1.x + gB1.x, -1.0f), 1.0f);
                y1.y = fminf(fmaxf(t1.y + gB1.y, -1.0f), 1.0f);
                float* yr = outY + (size_t)(row0 + r) * 128;
                *(float2*)(yr + 2 * lane) = y0;
                *(float2*)(yr + 64 + 2 * lane) = y1;
            }
        }
        if (lane == 0) {
            #pragma unroll
            for (int r = 0; r < RPW; r++)
                if (row0 + r < NROW) outI[row0 + r] = (float)bc[r];
        }
        __syncwarp();
    }
}

extern "C" void kernel_launch(void* const* d_in, const int* in_sizes, int n_in,
                              void* d_out, int out_size)
{
    const float* x  = (const float*)d_in[0];
    const float* Wd = (const float*)d_in[1];
    const float* bd = (const float*)d_in[2];
    const float* Wp = (const float*)d_in[3];
    const float* bp = (const float*)d_in[4];
    const float* cb = (const float*)d_in[5];
    const float* Wo = (const float*)d_in[6];
    const float* bo = (const float*)d_in[7];
    const float* Wu = (const float*)d_in[8];
    const float* bu = (const float*)d_in[9];
    float* out = (float*)d_out;

    cudaFuncSetAttribute(vq_expert_kernel,
                         cudaFuncAttributeMaxDynamicSharedMemorySize, SMEM_BYTES);

    vq_precompute_kernel<<<257, 128>>>(cb, Wo, bo, Wu, bu);
    vq_expert_kernel<<<148, 384, SMEM_BYTES>>>(x, Wd, bd, Wp, bp, cb, out);
}

// round 7
// speedup vs baseline: 2.5339x; 1.0230x over previous
#include <cuda_runtime.h>
#include <cstdint>

// VQExpert fused kernel, round 7 = R6 with the divergent-shfl deadlock removed.
// R4 numerics (two-step z: REQUIRED for argmin exactness) + cp.async
// double-buffered x prefetch + bias-folded T table.
//   A: h = x@Wd^T + bd          (smem Wd, split-column lanes, f32x2)
//   B: z = h@Wp^T + bp          (lane = z-column)
//   C: idx = argmin ||c||^2 - 2 z.c
//   E: y = clamp(T[idx], -1, 1),  T = (cb@Wo^T)@Wu^T + (bo@Wu^T + bu)  [prologue]

typedef unsigned long long ull;
#define FULLMASK 0xffffffffu

constexpr int NROW   = 500000;
constexpr int WARPS  = 12;
constexpr int RPW    = 8;
constexpr int TILE   = WARPS * RPW;              // 96
constexpr int NTILES = (NROW + TILE - 1) / TILE; // 5209

// smem layout (floats)
constexpr int O_WD2 = 0;          // 128x128: [(k>>1)*256 + j*2 + (k&1)]
constexpr int O_WP2 = 16384;      // 32x128 quad-packed: [(k>>2)*128 + c*4 + (k&3)]
constexpr int O_CB  = 20480;      // codebook quad-packed: [(d>>2)*1024 + c*4 + (d&3)]
constexpr int O_CN  = 28672;      // 256 code norms
constexpr int O_BD  = 28928;
constexpr int O_BP  = 29056;
constexpr int O_TS  = 29088;      // 12 warps x 2 bufs x (8 rows x 128)
constexpr int SMEM_FLOATS = O_TS + WARPS * 2 * RPW * 128;   // 53664
constexpr int SMEM_BYTES  = SMEM_FLOATS * 4;                // 214,656 B

__device__ float g_T[256 * 128];   // fused codebook->output table (bias folded)

__device__ __forceinline__ ull ffma2(ull a, ull b, ull c) {
    ull d;
    asm("fma.rn.f32x2 %0, %1, %2, %3;" : "=l"(d) : "l"(a), "l"(b), "l"(c));
    return d;
}
__device__ __forceinline__ float f2sum(ull v) {
    float a, b;
    asm("mov.b64 {%0, %1}, %2;" : "=f"(a), "=f"(b) : "l"(v));
    return a + b;
}
__device__ __forceinline__ void cpa16(uint32_t daddr, const void* g) {
    asm volatile("cp.async.ca.shared.global [%0], [%1], 16;" :: "r"(daddr), "l"(g));
}
__device__ __forceinline__ void cpa_commit() {
    asm volatile("cp.async.commit_group;");
}
__device__ __forceinline__ void cpa_wait1() {
    asm volatile("cp.async.wait_group 1;");
}

// ---------------- prologue: build T with bias folded ----------------
__global__ void __launch_bounds__(128)
vq_precompute_kernel(const float* __restrict__ cb,
                     const float* __restrict__ Wo, const float* __restrict__ bo,
                     const float* __restrict__ Wu, const float* __restrict__ bu)
{
    __shared__ float v[128];
    const int i = threadIdx.x;
    const int c = blockIdx.x;
    // v[j] = dot(cb[c], Wo[j])
    float s = 0.f;
    #pragma unroll 8
    for (int d = 0; d < 32; d++) s = fmaf(cb[c * 32 + d], Wo[i * 32 + d], s);
    v[i] = s;
    __syncthreads();
    // T[c][i] = dot(v, Wu[i]) + (bu[i] + dot(bo, Wu[i]))
    float t = 0.f, Bi = bu[i];
    #pragma unroll 8
    for (int j = 0; j < 128; j++) {
        t  = fmaf(v[j],  Wu[i * 128 + j], t);
        Bi = fmaf(bo[j], Wu[i * 128 + j], Bi);
    }
    g_T[c * 128 + i] = t + Bi;
}

// ---------------- main kernel ----------------
__global__ void __launch_bounds__(384, 1)
vq_expert_kernel(const float* __restrict__ x,
                 const float* __restrict__ Wd, const float* __restrict__ bd,
                 const float* __restrict__ Wp, const float* __restrict__ bp,
                 const float* __restrict__ cb,
                 float* __restrict__ out)
{
    extern __shared__ float sm[];
    const int tid = threadIdx.x;

    for (int i = tid; i < 128 * 128; i += 384) {
        int j = i >> 7, k = i & 127;
        sm[O_WD2 + (k >> 1) * 256 + j * 2 + (k & 1)] = Wd[i];
    }
    for (int i = tid; i < 4096; i += 384) {
        int c = i >> 7, k = i & 127;
        sm[O_WP2 + (k >> 2) * 128 + c * 4 + (k & 3)] = Wp[i];
    }
    for (int i = tid; i < 256 * 32; i += 384) {
        int c = i >> 5, d = i & 31;
        sm[O_CB + (d >> 2) * 1024 + c * 4 + (d & 3)] = cb[i];
    }
    for (int c = tid; c < 256; c += 384) {
        float s = 0.f;
        #pragma unroll 8
        for (int d = 0; d < 32; d++) { float v = cb[c * 32 + d]; s = fmaf(v, v, s); }
        sm[O_CN + c] = s;
    }
    if (tid < 128) sm[O_BD + tid] = bd[tid];
    else if (tid < 160) sm[O_BP + tid - 128] = bp[tid - 128];
    if (blockIdx.x == 0 && tid == 0)
        out[(size_t)NROW * 128 + NROW] = 0.0f;    // commit_loss == 0 exactly
    __syncthreads();

    const int wid  = tid >> 5;
    const int lane = tid & 31;
    float* stripe0 = sm + O_TS + (wid * 2) * (RPW * 128);

    const float2 bd0 = *(const float2*)(sm + O_BD + 2 * lane);
    const float2 bd1 = *(const float2*)(sm + O_BD + 64 + 2 * lane);
    const float  bpv = sm[O_BP + lane];
    float cn[8];
    #pragma unroll
    for (int i = 0; i < 8; i++) cn[i] = sm[O_CN + i * 32 + lane];

    float* outY = out;
    float* outI = out + (size_t)NROW * 128;
    const int tstride = gridDim.x;

    // smem u32 addresses of the two x-buffers for this lane
    uint32_t sb0 = (uint32_t)__cvta_generic_to_shared(stripe0 + 4 * lane);
    uint32_t sb1 = sb0 + (uint32_t)(RPW * 128 * 4);

    // prefetch tile 0 into buf 0
    {
        int row0 = blockIdx.x * TILE + wid * RPW;
        #pragma unroll
        for (int r = 0; r < RPW; r++)
            if (row0 + r < NROW)
                cpa16(sb0 + r * 512, x + (size_t)(row0 + r) * 128 + 4 * lane);
        cpa_commit();
    }

    int pb = 0;
    for (int tile = blockIdx.x; tile < NTILES; tile += tstride, pb ^= 1) {
        const int row0 = tile * TILE + wid * RPW;
        const bool full = (row0 + RPW <= NROW);

        // issue prefetch of next tile into the other buffer
        {
            int nrow0 = (tile + tstride) * TILE + wid * RPW;
            uint32_t nb = (pb ^ 1) ? sb1 : sb0;
            #pragma unroll
            for (int r = 0; r < RPW; r++)
                if (nrow0 + r < NROW)
                    cpa16(nb + r * 512, x + (size_t)(nrow0 + r) * 128 + 4 * lane);
            cpa_commit();
        }
        cpa_wait1();            // current tile's x is in smem (own lane's copies)
        __syncwarp();           // order all lanes' completed copies for the warp

        float* myts = stripe0 + pb * (RPW * 128);
        if (row0 >= NROW) continue;

        // -------- phase A: h = x @ Wd^T (+bd) --------
        ull acc[RPW][4];
        #pragma unroll
        for (int r = 0; r < RPW; r++)
            #pragma unroll
            for (int t = 0; t < 4; t++) acc[r][t] = 0ull;

        #pragma unroll 2
        for (int pp = 0; pp < 32; pp++) {
            const float* b0 = sm + O_WD2 + (2 * pp) * 256;
            const float* b1 = b0 + 256;
            ulonglong2 wa0 = *(const ulonglong2*)(b0 + 4 * lane);
            ulonglong2 wb0 = *(const ulonglong2*)(b0 + 128 + 4 * lane);
            ulonglong2 wa1 = *(const ulonglong2*)(b1 + 4 * lane);
            ulonglong2 wb1 = *(const ulonglong2*)(b1 + 128 + 4 * lane);
            #pragma unroll
            for (int r = 0; r < RPW; r++) {
                ulonglong2 xv = *(const ulonglong2*)(myts + r * 128 + 4 * pp);
                acc[r][0] = ffma2(xv.x, wa0.x, acc[r][0]);
                acc[r][1] = ffma2(xv.x, wa0.y, acc[r][1]);
                acc[r][2] = ffma2(xv.x, wb0.x, acc[r][2]);
                acc[r][3] = ffma2(xv.x, wb0.y, acc[r][3]);
                acc[r][0] = ffma2(xv.y, wa1.x, acc[r][0]);
                acc[r][1] = ffma2(xv.y, wa1.y, acc[r][1]);
                acc[r][2] = ffma2(xv.y, wb1.x, acc[r][2]);
                acc[r][3] = ffma2(xv.y, wb1.y, acc[r][3]);
            }
        }
        __syncwarp();
        #pragma unroll
        for (int r = 0; r < RPW; r++) {
            float2 h0, h1;
            h0.x = bd0.x + f2sum(acc[r][0]);
            h0.y = bd0.y + f2sum(acc[r][1]);
            h1.x = bd1.x + f2sum(acc[r][2]);
            h1.y = bd1.y + f2sum(acc[r][3]);
            *(float2*)(myts + r * 128 + 2 * lane) = h0;
            *(float2*)(myts + r * 128 + 64 + 2 * lane) = h1;
        }
        __syncwarp();

        // -------- phase B: z = h @ Wp^T (+bp), lane = z-column --------
        ull za[RPW];
        #pragma unroll
        for (int r = 0; r < RPW; r++) za[r] = 0ull;
        #pragma unroll 4
        for (int kq = 0; kq < 32; kq++) {
            ulonglong2 w = *(const ulonglong2*)(sm + O_WP2 + kq * 128 + 4 * lane);
            #pragma unroll
            for (int r = 0; r < RPW; r++) {
                ulonglong2 h2 = *(const ulonglong2*)(myts + r * 128 + 4 * kq);
                za[r] = ffma2(h2.x, w.x, za[r]);
                za[r] = ffma2(h2.y, w.y, za[r]);
            }
        }
        __syncwarp();
        #pragma unroll
        for (int r = 0; r < RPW; r++)
            myts[r * 128 + lane] = bpv + f2sum(za[r]);   // z in cols 0..31
        __syncwarp();

        // -------- phase C: argmin_c ||c||^2 - 2 z.c, 4 rows per pass --------
        int bc[RPW];
        #pragma unroll
        for (int hh = 0; hh < RPW / 4; hh++) {
            ull da[4][8];
            #pragma unroll
            for (int r = 0; r < 4; r++)
                #pragma unroll
                for (int i = 0; i < 8; i++) da[r][i] = 0ull;

            #pragma unroll 4
            for (int dq = 0; dq < 8; dq++) {
                ulonglong2 zq[4];
                #pragma unroll
                for (int r = 0; r < 4; r++)
                    zq[r] = *(const ulonglong2*)(myts + (hh * 4 + r) * 128 + 4 * dq);
                #pragma unroll
                for (int i = 0; i < 8; i++) {
                    ulonglong2 c2 = *(const ulonglong2*)(sm + O_CB + dq * 1024 + (i * 32 + lane) * 4);
                    #pragma unroll
                    for (int r = 0; r < 4; r++) {
                        da[r][i] = ffma2(zq[r].x, c2.x, da[r][i]);
                        da[r][i] = ffma2(zq[r].y, c2.y, da[r][i]);
                    }
                }
            }
            #pragma unroll
            for (int r = 0; r < 4; r++) {
                float bs = 3.4e38f; int bi = 0;
                #pragma unroll
                for (int i = 0; i < 8; i++) {
                    float s = cn[i] - 2.0f * f2sum(da[r][i]);
                    int c = (i << 5) | lane;
                    if (s < bs) { bs = s; bi = c; }
                }
                #pragma unroll
                for (int off = 16; off > 0; off >>= 1) {
                    float s2 = __shfl_xor_sync(FULLMASK, bs, off);
                    int   c2 = __shfl_xor_sync(FULLMASK, bi, off);
                    if (s2 < bs || (s2 == bs && c2 < bi)) { bs = s2; bi = c2; }
                }
                bc[hh * 4 + r] = bi;   // warp-uniform
            }
        }

        // -------- epilogue: y = clamp(T[bc], -1, 1) (bias pre-folded) --------
        #pragma unroll
        for (int r = 0; r < RPW; r++) {
            if (full || row0 + r < NROW) {
                float4 t = ((const float4*)(g_T + bc[r] * 128))[lane];
                float4 y;
                y.x = fminf(fmaxf(t.x, -1.0f), 1.0f);
                y.y = fminf(fmaxf(t.y, -1.0f), 1.0f);
                y.z = fminf(fmaxf(t.z, -1.0f), 1.0f);
                y.w = fminf(fmaxf(t.w, -1.0f), 1.0f);
                ((float4*)(outY + (size_t)(row0 + r) * 128))[lane] = y;
            }
        }
        if (lane == 0) {
            #pragma unroll
            for (int r = 0; r < RPW; r++)
                if (row0 + r < NROW) outI[row0 + r] = (float)bc[r];
        }
        __syncwarp();
    }
}

extern "C" void kernel_launch(void* const* d_in, const int* in_sizes, int n_in,
                              void* d_out, int out_size)
{
    const float* x  = (const float*)d_in[0];
    const float* Wd = (const float*)d_in[1];
    const float* bd = (const float*)d_in[2];
    const float* Wp = (const float*)d_in[3];
    const float* bp = (const float*)d_in[4];
    const float* cb = (const float*)d_in[5];
    const float* Wo = (const float*)d_in[6];
    const float* bo = (const float*)d_in[7];
    const float* Wu = (const float*)d_in[8];
    const float* bu = (const float*)d_in[9];
    float* out = (float*)d_out;

    cudaFuncSetAttribute(vq_expert_kernel,
                         cudaFuncAttributeMaxDynamicSharedMemorySize, SMEM_BYTES);

    vq_precompute_kernel<<<256, 128>>>(cb, Wo, bo, Wu, bu);
    vq_expert_kernel<<<148, 384, SMEM_BYTES>>>(x, Wd, bd, Wp, bp, cb, out);
}